// round 3
// baseline (speedup 1.0000x reference)
#include <cuda_runtime.h>
#include <math.h>

#define NW   32     // waves per set
#define BB   64     // batch
#define TT   8192   // time samples
#define KCH  16     // K chunks
#define CK   512    // K per chunk
#define TK   64     // K per smem tile (floats)
#define NT   (CK / TK)   // tiles per chunk = 8
#define K2   32     // float2 (k-even,k-odd) per tile row
#define PITCH 34    // smem pitch in float2 (pad 32 -> 34; keeps 16B alignment)

typedef unsigned long long u64;
typedef unsigned int u32;

// ---------------- device scratch (no allocation allowed) ----------------
__device__ float  g_pp[KCH * BB * NW * NW];    // partial P.P^T  per chunk  (4 MB)
__device__ float  g_pn[KCH * BB * NW * NW];    // partial P.Q^T  per chunk  (4 MB)
__device__ float  g_sum[KCH * 2 * BB * NW];    // partial row sums (set 0=P,1=Q)
__device__ float  g_sq [KCH * 2 * BB * NW];    // partial row sum-of-squares
__device__ float  g_s  [2 * BB * NW];          // combined sx
__device__ float  g_var[2 * BB * NW];          // T*sx2 - sx^2
__device__ double g_dmat[2 * NW * NW];         // d_pp, d_pn

// ---------------- packed f32x2 helpers (PTX-only; ptxas won't fuse) ----------------
__device__ __forceinline__ u64 ffma2(u64 a, u64 b, u64 c) {
    u64 d;
    asm("fma.rn.f32x2 %0, %1, %2, %3;" : "=l"(d) : "l"(a), "l"(b), "l"(c));
    return d;
}
__device__ __forceinline__ float hsum2(u64 a) {
    float lo, hi;
    asm("mov.b64 {%0, %1}, %2;" : "=f"(lo), "=f"(hi) : "l"(a));
    return lo + hi;
}

// ============================================================================
// Kernel 1: fused batched GEMMs (PP + PN) + row statistics.
// grid (KCH, BB), block 128.  warps 0-1: PP, warps 2-3: PN, 4x4 f32x2 micro.
// SMEM tiles transposed as float2: sm[k2][n] = (X[n][2k2], X[n][2k2+1]).
// ============================================================================
__global__ void __launch_bounds__(128)
k_gemm(const float* __restrict__ P, const float* __restrict__ Q) {
    __shared__ float2 smA[K2][PITCH];   // P tile
    __shared__ float2 smB[K2][PITCH];   // Q tile

    const int tid   = threadIdx.x;
    const int chunk = blockIdx.x;
    const int b     = blockIdx.y;

    // ---- loader role: thread owns row lrow, quad lq (4 threads per row) ----
    const int lrow = tid >> 2;
    const int lq   = tid & 3;
    const float* pRow = P + ((size_t)lrow * BB + b) * TT + (size_t)chunk * CK + lq * 4;
    const float* qRow = Q + ((size_t)lrow * BB + b) * TT + (size_t)chunk * CK + lq * 4;

    // ---- compute role ----
    const int warp = tid >> 5;
    const int lane = tid & 31;
    const int grp  = warp >> 1;            // 0 = PP, 1 = PN
    const int pwp  = warp & 1;
    const int tm   = lane >> 2;            // 0..7
    const int tn   = (lane & 3) + 4 * pwp; // 0..7

    const u32 sAu = (u32)__cvta_generic_to_shared(&smA[0][0]);
    const u32 sBu = (u32)__cvta_generic_to_shared(&smB[0][0]);
    const u32 aBase = sAu + (u32)(4 * tn) * 8;
    const u32 bBase = (grp ? sBu : sAu) + (u32)(4 * tm) * 8;

    u64 acc[4][4];
#pragma unroll
    for (int i = 0; i < 4; i++)
#pragma unroll
        for (int j = 0; j < 4; j++) acc[i][j] = 0ull;

    float sP = 0.f, q2P = 0.f, sQ = 0.f, q2Q = 0.f;

    for (int t = 0; t < NT; t++) {
        // global loads (overlap with previous tile's compute)
        float4 vp[4], vq[4];
        const float* pp = pRow + t * TK;
        const float* qq = qRow + t * TK;
#pragma unroll
        for (int u = 0; u < 4; u++) {
            vp[u] = __ldg((const float4*)(pp + u * 16));
            vq[u] = __ldg((const float4*)(qq + u * 16));
        }
        __syncthreads();   // previous compute done reading smem
#pragma unroll
        for (int u = 0; u < 4; u++) {
            int c4 = lq + 4 * u;
            smA[2 * c4    ][lrow] = make_float2(vp[u].x, vp[u].y);
            smA[2 * c4 + 1][lrow] = make_float2(vp[u].z, vp[u].w);
            smB[2 * c4    ][lrow] = make_float2(vq[u].x, vq[u].y);
            smB[2 * c4 + 1][lrow] = make_float2(vq[u].z, vq[u].w);
            sP  += vp[u].x + vp[u].y + vp[u].z + vp[u].w;
            q2P += vp[u].x * vp[u].x + vp[u].y * vp[u].y + vp[u].z * vp[u].z + vp[u].w * vp[u].w;
            sQ  += vq[u].x + vq[u].y + vq[u].z + vq[u].w;
            q2Q += vq[u].x * vq[u].x + vq[u].y * vq[u].y + vq[u].z * vq[u].z + vq[u].w * vq[u].w;
        }
        __syncthreads();   // tile visible

        u32 aA = aBase, bA = bBase;
#pragma unroll 8
        for (int k2 = 0; k2 < K2; k2++) {
            u64 a0, a1, a2, a3, b0, b1, b2, b3;
            asm volatile("ld.shared.v2.u64 {%0,%1},[%2];" : "=l"(a0), "=l"(a1) : "r"(aA));
            asm volatile("ld.shared.v2.u64 {%0,%1},[%2];" : "=l"(a2), "=l"(a3) : "r"(aA + 16));
            asm volatile("ld.shared.v2.u64 {%0,%1},[%2];" : "=l"(b0), "=l"(b1) : "r"(bA));
            asm volatile("ld.shared.v2.u64 {%0,%1},[%2];" : "=l"(b2), "=l"(b3) : "r"(bA + 16));
            acc[0][0] = ffma2(a0, b0, acc[0][0]);
            acc[0][1] = ffma2(a0, b1, acc[0][1]);
            acc[0][2] = ffma2(a0, b2, acc[0][2]);
            acc[0][3] = ffma2(a0, b3, acc[0][3]);
            acc[1][0] = ffma2(a1, b0, acc[1][0]);
            acc[1][1] = ffma2(a1, b1, acc[1][1]);
            acc[1][2] = ffma2(a1, b2, acc[1][2]);
            acc[1][3] = ffma2(a1, b3, acc[1][3]);
            acc[2][0] = ffma2(a2, b0, acc[2][0]);
            acc[2][1] = ffma2(a2, b1, acc[2][1]);
            acc[2][2] = ffma2(a2, b2, acc[2][2]);
            acc[2][3] = ffma2(a2, b3, acc[2][3]);
            acc[3][0] = ffma2(a3, b0, acc[3][0]);
            acc[3][1] = ffma2(a3, b1, acc[3][1]);
            acc[3][2] = ffma2(a3, b2, acc[3][2]);
            acc[3][3] = ffma2(a3, b3, acc[3][3]);
            aA += PITCH * 8;
            bA += PITCH * 8;
        }
    }

    // ---- write GEMM partials ----
    float* gout = (grp ? g_pn : g_pp) + ((size_t)chunk * BB + b) * NW * NW;
#pragma unroll
    for (int i = 0; i < 4; i++)
#pragma unroll
        for (int j = 0; j < 4; j++)
            gout[(4 * tn + i) * NW + (4 * tm + j)] = hsum2(acc[i][j]);

    // ---- reduce stats over the 4 loader lanes of each row, then write ----
#pragma unroll
    for (int off = 1; off < 4; off <<= 1) {
        sP  += __shfl_xor_sync(0xffffffffu, sP,  off);
        q2P += __shfl_xor_sync(0xffffffffu, q2P, off);
        sQ  += __shfl_xor_sync(0xffffffffu, sQ,  off);
        q2Q += __shfl_xor_sync(0xffffffffu, q2Q, off);
    }
    if (lq == 0) {
        int base0 = ((chunk * 2 + 0) * BB + b) * NW + lrow;
        int base1 = ((chunk * 2 + 1) * BB + b) * NW + lrow;
        g_sum[base0] = sP;  g_sq[base0] = q2P;
        g_sum[base1] = sQ;  g_sq[base1] = q2Q;
    }
}

// ============================================================================
// Kernel 2: fold stat partials, compute variance terms.  4096 threads.
// ============================================================================
__global__ void k_stats() {
    int id = blockIdx.x * blockDim.x + threadIdx.x;
    if (id >= 2 * BB * NW) return;
    int set = id / (BB * NW);
    int rem = id % (BB * NW);
    float s = 0.f, s2 = 0.f;
#pragma unroll
    for (int c = 0; c < KCH; c++) {
        int idx = (c * 2 + set) * (BB * NW) + rem;
        s  += g_sum[idx];
        s2 += g_sq[idx];
    }
    g_s[id]   = s;
    g_var[id] = (float)TT * s2 - s * s;
}

// ============================================================================
// Kernel 3: fold GEMM partials, compute d[n][m] = mean_b (1 - pearson).
// 2048 threads: (set, n, m).
// ============================================================================
__global__ void k_dmat() {
    int id = blockIdx.x * blockDim.x + threadIdx.x;
    if (id >= 2 * NW * NW) return;
    int set = id >> 10;
    int nm  = id & 1023;
    int n   = nm >> 5;
    int m   = nm & 31;
    const float* gsrc = set ? g_pn : g_pp;
    const float* sY = g_s   + set * (BB * NW);
    const float* vY = g_var + set * (BB * NW);
    double acc = 0.0;
    for (int b = 0; b < BB; b++) {
        float sxy = 0.f;
#pragma unroll
        for (int c = 0; c < KCH; c++)
            sxy += gsrc[((size_t)(c * BB + b)) * (NW * NW) + nm];
        float sx = g_s[b * NW + n],  sy = sY[b * NW + m];
        float vx = g_var[b * NW + n], vy = vY[b * NW + m];
        float r = ((float)TT * sxy - sx * sy) / sqrtf(vx * vy);
        acc += (double)(1.f - r);
    }
    g_dmat[id] = acc * (1.0 / (double)BB);
}

// ============================================================================
// Kernel 4: final reduction: log10(sum_{i<j} e^{dpp/tau} / sum e^{dpn/tau} + 1)
// ============================================================================
__global__ void k_final(float* __restrict__ out) {
    __shared__ double sp[256], sn[256];
    int t = threadIdx.x;
    double ap = 0.0, an = 0.0;
    for (int idx = t; idx < NW * NW; idx += 256) {
        int i = idx >> 5, j = idx & 31;
        if (j > i) ap += exp(g_dmat[idx] * 12.5);           // 1/TAU = 12.5
        an += exp(g_dmat[NW * NW + idx] * 12.5);
    }
    sp[t] = ap; sn[t] = an;
    __syncthreads();
    for (int s = 128; s > 0; s >>= 1) {
        if (t < s) { sp[t] += sp[t + s]; sn[t] += sn[t + s]; }
        __syncthreads();
    }
    if (t == 0) out[0] = (float)log10(sp[0] / sn[0] + 1.0);
}

// ============================================================================
extern "C" void kernel_launch(void* const* d_in, const int* in_sizes, int n_in,
                              void* d_out, int out_size) {
    const float* P = (const float*)d_in[0];
    const float* Q = (const float*)d_in[1];
    k_gemm<<<dim3(KCH, BB), 128>>>(P, Q);
    k_stats<<<16, 256>>>();
    k_dmat<<<8, 256>>>();
    k_final<<<1, 256>>>((float*)d_out);
}

// round 4
// speedup vs baseline: 1.4413x; 1.4413x over previous
#include <cuda_runtime.h>
#include <math.h>

#define NW   32     // waves per set
#define BB   64     // batch
#define TT   8192   // time samples
#define KCH  16     // K chunks
#define CK   512    // K per chunk
#define TK   64     // K per smem tile (floats)
#define NT   (CK / TK)   // tiles per chunk = 8
#define K2   32     // float2 (k-even,k-odd) per tile row
#define PITCH 34    // smem pitch in float2 (pad 32 -> 34; keeps 16B alignment)

typedef unsigned long long u64;
typedef unsigned int u32;

// ---------------- device scratch (no allocation allowed) ----------------
__device__ float  g_pp[KCH * BB * NW * NW];    // partial P.P^T  per chunk  (4 MB)
__device__ float  g_pn[KCH * BB * NW * NW];    // partial P.Q^T  per chunk  (4 MB)
__device__ float  g_sum[KCH * 2 * BB * NW];    // partial row sums (set 0=P,1=Q)
__device__ float  g_sq [KCH * 2 * BB * NW];    // partial row sum-of-squares
__device__ double g_tot[2];                    // pos_total, neg_total

// ---------------- packed f32x2 helpers (PTX-only; ptxas won't fuse) ----------------
__device__ __forceinline__ u64 ffma2(u64 a, u64 b, u64 c) {
    u64 d;
    asm("fma.rn.f32x2 %0, %1, %2, %3;" : "=l"(d) : "l"(a), "l"(b), "l"(c));
    return d;
}
__device__ __forceinline__ float hsum2(u64 a) {
    float lo, hi;
    asm("mov.b64 {%0, %1}, %2;" : "=f"(lo), "=f"(hi) : "l"(a));
    return lo + hi;
}

// ============================================================================
// Kernel 1: fused batched GEMMs (PP + PN) + row statistics.
// grid (KCH, BB), block 128.  warps 0-1: PP, warps 2-3: PN, 4x4 f32x2 micro.
// SMEM tiles transposed as float2: sm[k2][n] = (X[n][2k2], X[n][2k2+1]).
// Tile t+1 is prefetched into registers BEFORE computing tile t (hides DRAM).
// ============================================================================
__global__ void __launch_bounds__(128)
k_gemm(const float* __restrict__ P, const float* __restrict__ Q) {
    __shared__ float2 smA[K2][PITCH];   // P tile
    __shared__ float2 smB[K2][PITCH];   // Q tile

    const int tid   = threadIdx.x;
    const int chunk = blockIdx.x;
    const int b     = blockIdx.y;

    if (chunk == 0 && b == 0 && tid < 2) g_tot[tid] = 0.0;  // zero totals per launch

    // ---- loader role: thread owns row lrow, quad lq (4 threads per row) ----
    const int lrow = tid >> 2;
    const int lq   = tid & 3;
    const float* pRow = P + ((size_t)lrow * BB + b) * TT + (size_t)chunk * CK + lq * 4;
    const float* qRow = Q + ((size_t)lrow * BB + b) * TT + (size_t)chunk * CK + lq * 4;

    // ---- compute role ----
    const int warp = tid >> 5;
    const int lane = tid & 31;
    const int grp  = warp >> 1;            // 0 = PP, 1 = PN
    const int pwp  = warp & 1;
    const int tm   = lane >> 2;            // 0..7
    const int tn   = (lane & 3) + 4 * pwp; // 0..7

    const u32 sAu = (u32)__cvta_generic_to_shared(&smA[0][0]);
    const u32 sBu = (u32)__cvta_generic_to_shared(&smB[0][0]);
    const u32 aBase = sAu + (u32)(4 * tn) * 8;
    const u32 bBase = (grp ? sBu : sAu) + (u32)(4 * tm) * 8;

    u64 acc[4][4];
#pragma unroll
    for (int i = 0; i < 4; i++)
#pragma unroll
        for (int j = 0; j < 4; j++) acc[i][j] = 0ull;

    float sP = 0.f, q2P = 0.f, sQ = 0.f, q2Q = 0.f;

    // preload tile 0
    float4 vp[4], vq[4];
#pragma unroll
    for (int u = 0; u < 4; u++) {
        vp[u] = __ldg((const float4*)(pRow + u * 16));
        vq[u] = __ldg((const float4*)(qRow + u * 16));
    }

    for (int t = 0; t < NT; t++) {
        __syncthreads();   // previous compute done reading smem
#pragma unroll
        for (int u = 0; u < 4; u++) {
            int c4 = lq + 4 * u;
            smA[2 * c4    ][lrow] = make_float2(vp[u].x, vp[u].y);
            smA[2 * c4 + 1][lrow] = make_float2(vp[u].z, vp[u].w);
            smB[2 * c4    ][lrow] = make_float2(vq[u].x, vq[u].y);
            smB[2 * c4 + 1][lrow] = make_float2(vq[u].z, vq[u].w);
            sP  += vp[u].x + vp[u].y + vp[u].z + vp[u].w;
            q2P += vp[u].x * vp[u].x + vp[u].y * vp[u].y + vp[u].z * vp[u].z + vp[u].w * vp[u].w;
            sQ  += vq[u].x + vq[u].y + vq[u].z + vq[u].w;
            q2Q += vq[u].x * vq[u].x + vq[u].y * vq[u].y + vq[u].z * vq[u].z + vq[u].w * vq[u].w;
        }
        __syncthreads();   // tile visible

        // prefetch next tile BEFORE compute (overlaps DRAM with FFMA2)
        float4 wp[4], wq[4];
        if (t + 1 < NT) {
            const float* pp = pRow + (t + 1) * TK;
            const float* qq = qRow + (t + 1) * TK;
#pragma unroll
            for (int u = 0; u < 4; u++) {
                wp[u] = __ldg((const float4*)(pp + u * 16));
                wq[u] = __ldg((const float4*)(qq + u * 16));
            }
        }

        u32 aA = aBase, bA = bBase;
#pragma unroll 8
        for (int k2 = 0; k2 < K2; k2++) {
            u64 a0, a1, a2, a3, b0, b1, b2, b3;
            asm volatile("ld.shared.v2.u64 {%0,%1},[%2];" : "=l"(a0), "=l"(a1) : "r"(aA));
            asm volatile("ld.shared.v2.u64 {%0,%1},[%2];" : "=l"(a2), "=l"(a3) : "r"(aA + 16));
            asm volatile("ld.shared.v2.u64 {%0,%1},[%2];" : "=l"(b0), "=l"(b1) : "r"(bA));
            asm volatile("ld.shared.v2.u64 {%0,%1},[%2];" : "=l"(b2), "=l"(b3) : "r"(bA + 16));
            acc[0][0] = ffma2(a0, b0, acc[0][0]);
            acc[0][1] = ffma2(a0, b1, acc[0][1]);
            acc[0][2] = ffma2(a0, b2, acc[0][2]);
            acc[0][3] = ffma2(a0, b3, acc[0][3]);
            acc[1][0] = ffma2(a1, b0, acc[1][0]);
            acc[1][1] = ffma2(a1, b1, acc[1][1]);
            acc[1][2] = ffma2(a1, b2, acc[1][2]);
            acc[1][3] = ffma2(a1, b3, acc[1][3]);
            acc[2][0] = ffma2(a2, b0, acc[2][0]);
            acc[2][1] = ffma2(a2, b1, acc[2][1]);
            acc[2][2] = ffma2(a2, b2, acc[2][2]);
            acc[2][3] = ffma2(a2, b3, acc[2][3]);
            acc[3][0] = ffma2(a3, b0, acc[3][0]);
            acc[3][1] = ffma2(a3, b1, acc[3][1]);
            acc[3][2] = ffma2(a3, b2, acc[3][2]);
            acc[3][3] = ffma2(a3, b3, acc[3][3]);
            aA += PITCH * 8;
            bA += PITCH * 8;
        }

#pragma unroll
        for (int u = 0; u < 4; u++) { vp[u] = wp[u]; vq[u] = wq[u]; }
    }

    // ---- write GEMM partials ----
    float* gout = (grp ? g_pn : g_pp) + ((size_t)chunk * BB + b) * NW * NW;
#pragma unroll
    for (int i = 0; i < 4; i++)
#pragma unroll
        for (int j = 0; j < 4; j++)
            gout[(4 * tn + i) * NW + (4 * tm + j)] = hsum2(acc[i][j]);

    // ---- reduce stats over the 4 loader lanes of each row, then write ----
#pragma unroll
    for (int off = 1; off < 4; off <<= 1) {
        sP  += __shfl_xor_sync(0xffffffffu, sP,  off);
        q2P += __shfl_xor_sync(0xffffffffu, q2P, off);
        sQ  += __shfl_xor_sync(0xffffffffu, sQ,  off);
        q2Q += __shfl_xor_sync(0xffffffffu, q2Q, off);
    }
    if (lq == 0) {
        int base0 = ((chunk * 2 + 0) * BB + b) * NW + lrow;
        int base1 = ((chunk * 2 + 1) * BB + b) * NW + lrow;
        g_sum[base0] = sP;  g_sq[base0] = q2P;
        g_sum[base1] = sQ;  g_sq[base1] = q2Q;
    }
}

// ============================================================================
// Kernel 2: fold stats + fold sxy partials + d = mean_b(1-r) + expf + reduce.
// grid (8, 2): blockIdx.y = set (0=PP,1=PN), blockIdx.x = 128-nm slice.
// Each block owns the FULL b-range for its nm slice -> no cross-block d.
// Adds block partial of sum(exp(d/tau)) into g_tot[set] (double atomics).
// ============================================================================
__global__ void __launch_bounds__(256) k_dmat() {
    const int set = blockIdx.y;
    const int blk = blockIdx.x;
    const int tid = threadIdx.x;

    __shared__ float s_sx[2][BB * NW];   // [0]=row stats (P), [1]=col stats (P or Q)
    __shared__ float s_rv[2][BB * NW];   // 1/sqrt(T*s2 - s^2)

#pragma unroll
    for (int side = 0; side < 2; side++) {
        int srcSet = side ? set : 0;
        for (int idx = tid; idx < BB * NW; idx += 256) {
            float s = 0.f, s2 = 0.f;
#pragma unroll
            for (int c = 0; c < KCH; c++) {
                int a = (c * 2 + srcSet) * (BB * NW) + idx;
                s  += g_sum[a];
                s2 += g_sq[a];
            }
            s_sx[side][idx] = s;
            s_rv[side][idx] = rsqrtf((float)TT * s2 - s * s);
        }
    }
    __syncthreads();

    const int half = tid >> 7;          // each half handles 32 b values
    const int nml  = tid & 127;
    const int nm   = blk * 128 + nml;
    const int n    = nm >> 5;
    const int m    = nm & 31;
    const float* src = set ? g_pn : g_pp;

    float acc = 0.f;
    const int b0 = half * 32;
#pragma unroll 4
    for (int b = b0; b < b0 + 32; b++) {
        float sxy = 0.f;
#pragma unroll
        for (int c = 0; c < KCH; c++)
            sxy += src[((size_t)(c * BB + b)) * (NW * NW) + nm];
        float r = ((float)TT * sxy - s_sx[0][b * NW + n] * s_sx[1][b * NW + m])
                  * s_rv[0][b * NW + n] * s_rv[1][b * NW + m];
        acc += 1.f - r;
    }

    __shared__ float s_red[256];
    s_red[tid] = acc;
    __syncthreads();

    __shared__ double s_d[256];
    double e = 0.0;
    if (half == 0) {
        float d = (acc + s_red[128 + nml]) * (1.f / (float)BB);
        bool keep = set ? true : (m > n);      // PP: strict upper triangle only
        if (keep) e = (double)expf(12.5f * d); // 1/TAU = 12.5
    }
    s_d[tid] = e;
    __syncthreads();
#pragma unroll
    for (int s = 128; s > 0; s >>= 1) {
        if (tid < s) s_d[tid] += s_d[tid + s];
        __syncthreads();
    }
    if (tid == 0) atomicAdd(&g_tot[set], s_d[0]);
}

// ============================================================================
// Kernel 3: trivial finisher.
// ============================================================================
__global__ void k_final(float* __restrict__ out) {
    out[0] = (float)log10(g_tot[0] / g_tot[1] + 1.0);
}

// ============================================================================
extern "C" void kernel_launch(void* const* d_in, const int* in_sizes, int n_in,
                              void* d_out, int out_size) {
    const float* P = (const float*)d_in[0];
    const float* Q = (const float*)d_in[1];
    k_gemm<<<dim3(KCH, BB), 128>>>(P, Q);
    k_dmat<<<dim3(8, 2), 256>>>();
    k_final<<<1, 1>>>((float*)d_out);
}

// round 7
// speedup vs baseline: 1.9541x; 1.3558x over previous
#include <cuda_runtime.h>
#include <cuda_bf16.h>
#include <math.h>

#define NW 32
#define BB 64
#define TT 8192
#define KCH 8
#define CK (TT / KCH)     // 1024
#define KT 64             // fp32 per K-tile
#define NT (CK / KT)      // 16 tiles

typedef unsigned int u32;

__device__ float  g_pp[KCH * BB * NW * NW];
__device__ float  g_pn[KCH * BB * NW * NW];
__device__ float  g_sum[KCH * 2 * BB * NW];
__device__ float  g_sq [KCH * 2 * BB * NW];
__device__ double g_tot[2];

__device__ __forceinline__ void ldsm4(u32& r0, u32& r1, u32& r2, u32& r3, u32 a) {
    asm volatile("ldmatrix.sync.aligned.m8n8.x4.shared.b16 {%0,%1,%2,%3}, [%4];"
                 : "=r"(r0), "=r"(r1), "=r"(r2), "=r"(r3) : "r"(a));
}
__device__ __forceinline__ void ldsm2(u32& r0, u32& r1, u32 a) {
    asm volatile("ldmatrix.sync.aligned.m8n8.x2.shared.b16 {%0,%1}, [%2];"
                 : "=r"(r0), "=r"(r1) : "r"(a));
}
__device__ __forceinline__ void mma16816(float* c, u32 a0, u32 a1, u32 a2, u32 a3,
                                         u32 b0, u32 b1) {
    asm volatile("mma.sync.aligned.m16n8k16.row.col.f32.bf16.bf16.f32 "
                 "{%0,%1,%2,%3}, {%4,%5,%6,%7}, {%8,%9}, {%0,%1,%2,%3};"
                 : "+f"(c[0]), "+f"(c[1]), "+f"(c[2]), "+f"(c[3])
                 : "r"(a0), "r"(a1), "r"(a2), "r"(a3), "r"(b0), "r"(b1));
}
__device__ __forceinline__ u32 bpack(float lo, float hi) {
    __nv_bfloat162 t = __float22bfloat162_rn(make_float2(lo, hi));
    return *(u32*)&t;
}

// ============================================================================
// Kernel 1: bf16 mma.sync fused GEMM (PP + PN) + exact fp32 row stats.
// grid (KCH, BB), 128 threads.  smem tile: [P(32); Q(32)] x 64 bf16 (128B rows,
// SW128 xor).  A operand = rows 0-31 of same tile (P read from HBM once).
// Warp w -> C cols [16w, 16w+16); 2x2 m16n8k16 tiles per k16.
// ============================================================================
__global__ void __launch_bounds__(128, 4)
k_gemm(const float* __restrict__ P, const float* __restrict__ Q) {
    __shared__ __align__(1024) char sm[64 * 128];   // 8 KB

    const int tid = threadIdx.x, lane = tid & 31, wid = tid >> 5;
    const int chunk = blockIdx.x, b = blockIdx.y;
    if (chunk == 0 && b == 0 && tid < 2) g_tot[tid] = 0.0;

    // ---- loader role: row r (0-31 P, 32-63 Q), half h of 64-float tile row ----
    const int r = tid >> 1, h = tid & 1;
    const int isQ = r >> 5, n = r & 31;
    const float* grow = (isQ ? Q : P) + ((size_t)n * BB + b) * TT + chunk * CK + h * 32;

    const u32 sbase = (u32)__cvta_generic_to_shared(sm);
    u32 stsaddr[4];
#pragma unroll
    for (int c = 0; c < 4; c++) {
        u32 o = (u32)(r * 128 + (h * 4 + c) * 16);
        stsaddr[c] = sbase + (o ^ ((o >> 3) & 0x70));
    }

    // ---- fragment base addresses (swizzle reduces to ^((row&7)<<4)) ----
    const int qd = lane >> 3, il = lane & 7;
    const u32 xm = (u32)(il << 4);
    u32 aB[2], bB[2];
#pragma unroll
    for (int mt = 0; mt < 2; mt++)
        aB[mt] = sbase + (u32)((16 * mt + (qd & 1) * 8 + il) * 128);
    const u32 c16A = (u32)((qd >> 1) * 16);
#pragma unroll
    for (int nt = 0; nt < 2; nt++)
        bB[nt] = sbase + (u32)((wid * 16 + nt * 8 + il) * 128);
    const u32 c16B = (u32)(((lane >> 3) & 1) * 16);

    float C[2][2][4];
#pragma unroll
    for (int i = 0; i < 2; i++)
#pragma unroll
        for (int j = 0; j < 2; j++)
#pragma unroll
            for (int k = 0; k < 4; k++) C[i][j][k] = 0.f;

    float acs = 0.f, acq = 0.f;

    // prologue: load tile 0 (32 fp32 per thread)
    float4 v[8];
#pragma unroll
    for (int u = 0; u < 8; u++) v[u] = __ldg((const float4*)grow + u);

    for (int t = 0; t < NT; t++) {
        __syncthreads();                        // prior mma done reading sm
#pragma unroll
        for (int c = 0; c < 4; c++) {
            float4 v0 = v[2 * c], v1 = v[2 * c + 1];
            uint4 w;
            w.x = bpack(v0.x, v0.y); w.y = bpack(v0.z, v0.w);
            w.z = bpack(v1.x, v1.y); w.w = bpack(v1.z, v1.w);
            asm volatile("st.shared.v4.b32 [%0], {%1,%2,%3,%4};"
                         :: "r"(stsaddr[c]), "r"(w.x), "r"(w.y), "r"(w.z), "r"(w.w));
            acs += (v0.x + v0.y) + (v0.z + v0.w) + (v1.x + v1.y) + (v1.z + v1.w);
            acq = fmaf(v0.x, v0.x, acq); acq = fmaf(v0.y, v0.y, acq);
            acq = fmaf(v0.z, v0.z, acq); acq = fmaf(v0.w, v0.w, acq);
            acq = fmaf(v1.x, v1.x, acq); acq = fmaf(v1.y, v1.y, acq);
            acq = fmaf(v1.z, v1.z, acq); acq = fmaf(v1.w, v1.w, acq);
        }
        __syncthreads();                        // tile visible

        if (t + 1 < NT) {                       // prefetch next (hides DRAM)
            const float4* src = (const float4*)(grow + (t + 1) * KT);
#pragma unroll
            for (int u = 0; u < 8; u++) v[u] = __ldg(src + u);
        }

#pragma unroll
        for (int j = 0; j < 4; j++) {           // 4 x k16 per tile
            u32 a[2][4], bq[2][2];
#pragma unroll
            for (int mt = 0; mt < 2; mt++)
                ldsm4(a[mt][0], a[mt][1], a[mt][2], a[mt][3],
                      aB[mt] + (((u32)(j * 32) + c16A) ^ xm));
#pragma unroll
            for (int nt = 0; nt < 2; nt++)
                ldsm2(bq[nt][0], bq[nt][1],
                      bB[nt] + (((u32)(j * 32) + c16B) ^ xm));
#pragma unroll
            for (int mt = 0; mt < 2; mt++)
#pragma unroll
                for (int nt = 0; nt < 2; nt++)
                    mma16816(C[mt][nt], a[mt][0], a[mt][1], a[mt][2], a[mt][3],
                             bq[nt][0], bq[nt][1]);
        }
    }

    // ---- write C partials (warps 0-1: PP, 2-3: PN) ----
    {
        float* g0 = (wid < 2 ? g_pp : g_pn) + ((size_t)(chunk * BB + b)) * (NW * NW);
        const int g = lane >> 2, tq = lane & 3;
        const int wcol = (wid & 1) * 16;
#pragma unroll
        for (int mt = 0; mt < 2; mt++)
#pragma unroll
            for (int nt = 0; nt < 2; nt++) {
                int row0 = 16 * mt + g;
                int cc = wcol + nt * 8 + 2 * tq;
                *(float2*)(g0 + row0 * NW + cc) =
                    make_float2(C[mt][nt][0], C[mt][nt][1]);
                *(float2*)(g0 + (row0 + 8) * NW + cc) =
                    make_float2(C[mt][nt][2], C[mt][nt][3]);
            }
    }

    // ---- stats: combine the two halves of each row, write ----
    acs += __shfl_xor_sync(0xffffffffu, acs, 1);
    acq += __shfl_xor_sync(0xffffffffu, acq, 1);
    if (h == 0) {
        int idx = (chunk * 2 + isQ) * (BB * NW) + b * NW + n;
        g_sum[idx] = acs;  g_sq[idx] = acq;
    }
}

// ============================================================================
// Kernel 2: fold stats + sxy partials -> d -> expf -> reduce into g_tot.
// ============================================================================
__global__ void __launch_bounds__(256) k_dmat() {
    const int set = blockIdx.y, blk = blockIdx.x, tid = threadIdx.x;
    __shared__ float s_sx[2][BB * NW], s_rv[2][BB * NW];
#pragma unroll
    for (int side = 0; side < 2; side++) {
        int srcSet = side ? set : 0;
        for (int idx = tid; idx < BB * NW; idx += 256) {
            float s = 0.f, s2 = 0.f;
#pragma unroll
            for (int c = 0; c < KCH; c++) {
                int a = (c * 2 + srcSet) * (BB * NW) + idx;
                s += g_sum[a]; s2 += g_sq[a];
            }
            s_sx[side][idx] = s;
            s_rv[side][idx] = rsqrtf((float)TT * s2 - s * s);
        }
    }
    __syncthreads();
    const int half = tid >> 7, nml = tid & 127, nm = blk * 128 + nml;
    const int n = nm >> 5, m = nm & 31;
    const float* src = set ? g_pn : g_pp;
    float acc = 0.f;
    const int b0 = half * 32;
#pragma unroll 4
    for (int b = b0; b < b0 + 32; b++) {
        float sxy = 0.f;
#pragma unroll
        for (int c = 0; c < KCH; c++)
            sxy += src[((size_t)(c * BB + b)) * (NW * NW) + nm];
        float r = ((float)TT * sxy - s_sx[0][b * NW + n] * s_sx[1][b * NW + m])
                  * s_rv[0][b * NW + n] * s_rv[1][b * NW + m];
        acc += 1.f - r;
    }
    __shared__ float s_red[256];
    s_red[tid] = acc;
    __syncthreads();
    __shared__ double s_d[256];
    double e = 0.0;
    if (half == 0) {
        float d = (acc + s_red[128 + nml]) * (1.f / (float)BB);
        bool keep = set ? true : (m > n);
        if (keep) e = (double)expf(12.5f * d);
    }
    s_d[tid] = e;
    __syncthreads();
#pragma unroll
    for (int s = 128; s > 0; s >>= 1) {
        if (tid < s) s_d[tid] += s_d[tid + s];
        __syncthreads();
    }
    if (tid == 0) atomicAdd(&g_tot[set], s_d[0]);
}

__global__ void k_final(float* __restrict__ out) {
    out[0] = (float)log10(g_tot[0] / g_tot[1] + 1.0);
}

extern "C" void kernel_launch(void* const* d_in, const int* in_sizes, int n_in,
                              void* d_out, int out_size) {
    const float* P = (const float*)d_in[0];
    const float* Q = (const float*)d_in[1];
    k_gemm<<<dim3(KCH, BB), 128>>>(P, Q);
    k_dmat<<<dim3(8, 2), 256>>>();
    k_final<<<1, 1>>>((float*)d_out);
}

// round 8
// speedup vs baseline: 2.8051x; 1.4355x over previous
#include <cuda_runtime.h>
#include <cuda_bf16.h>
#include <math.h>

#define NW 32
#define BB 64
#define TT 8192
#define KCH 8
#define CK (TT / KCH)     // 1024
#define KT 64             // fp32 per K-tile
#define NT (CK / KT)      // 16 tiles

typedef unsigned int u32;

__device__ float  g_pp[KCH * BB * NW * NW];
__device__ float  g_pn[KCH * BB * NW * NW];
__device__ float  g_sum[KCH * 2 * BB * NW];
__device__ float  g_sq [KCH * 2 * BB * NW];
__device__ double g_tot[2];

__device__ __forceinline__ void ldsm4(u32& r0, u32& r1, u32& r2, u32& r3, u32 a) {
    asm volatile("ldmatrix.sync.aligned.m8n8.x4.shared.b16 {%0,%1,%2,%3}, [%4];"
                 : "=r"(r0), "=r"(r1), "=r"(r2), "=r"(r3) : "r"(a));
}
__device__ __forceinline__ void ldsm2(u32& r0, u32& r1, u32 a) {
    asm volatile("ldmatrix.sync.aligned.m8n8.x2.shared.b16 {%0,%1}, [%2];"
                 : "=r"(r0), "=r"(r1) : "r"(a));
}
__device__ __forceinline__ void mma16816(float* c, u32 a0, u32 a1, u32 a2, u32 a3,
                                         u32 b0, u32 b1) {
    asm volatile("mma.sync.aligned.m16n8k16.row.col.f32.bf16.bf16.f32 "
                 "{%0,%1,%2,%3}, {%4,%5,%6,%7}, {%8,%9}, {%0,%1,%2,%3};"
                 : "+f"(c[0]), "+f"(c[1]), "+f"(c[2]), "+f"(c[3])
                 : "r"(a0), "r"(a1), "r"(a2), "r"(a3), "r"(b0), "r"(b1));
}
__device__ __forceinline__ u32 bpack(float lo, float hi) {
    __nv_bfloat162 t = __float22bfloat162_rn(make_float2(lo, hi));
    return *(u32*)&t;
}

// ============================================================================
// Kernel 1: bf16 mma.sync fused GEMM (PP + PN) + exact fp32 row stats.
// grid (KCH, BB), 128 threads.
// Loader: half-warp per fp32 row (COALESCED: 4 lines/warp instr). Thread owns
//   rows R_u = 8u + (tid>>4), u=0..7 (u<4: P, u>=4: Q), 16B slice li=tid&15.
// Smem: DOUBLE-buffered 64x128B bf16 tile (SW128 xor), ONE barrier per tile.
// Warp w -> C cols [16w,16w+16); 2x2 m16n8k16 per k16.
// ============================================================================
__global__ void __launch_bounds__(128, 4)
k_gemm(const float* __restrict__ P, const float* __restrict__ Q) {
    __shared__ __align__(1024) char sm[2][64 * 128];   // 2 x 8 KB

    const int tid = threadIdx.x, lane = tid & 31, wid = tid >> 5;
    const int chunk = blockIdx.x, b = blockIdx.y;
    if (chunk == 0 && b == 0 && tid < 2) g_tot[tid] = 0.0;

    // ---- loader plan ----
    const int lrow = tid >> 4;          // 0..7
    const int li   = tid & 15;          // 16B index within 256B fp32 row
    u32 goff[8];                        // element offsets (row n of P or Q)
    u32 sdst[8];                        // swizzled smem byte offsets (buf 0)
    const u32 sbase = (u32)__cvta_generic_to_shared(sm);
#pragma unroll
    for (int u = 0; u < 8; u++) {
        int n = 8 * (u & 3) + lrow;
        goff[u] = (u32)((n * BB + b) * TT + chunk * CK + li * 4);
        int R = 8 * u + lrow;
        sdst[u] = sbase + (u32)(R * 128 + ((li * 8) ^ (lrow << 4)));
    }

    // ---- fragment addresses (row-7 validated) ----
    const int qd = lane >> 3, il = lane & 7;
    const u32 xm = (u32)(il << 4);
    u32 aB[2], bB[2];
#pragma unroll
    for (int mt = 0; mt < 2; mt++)
        aB[mt] = sbase + (u32)((16 * mt + (qd & 1) * 8 + il) * 128);
    const u32 c16A = (u32)((qd >> 1) * 16);
#pragma unroll
    for (int nt = 0; nt < 2; nt++)
        bB[nt] = sbase + (u32)((wid * 16 + nt * 8 + il) * 128);
    const u32 c16B = (u32)(((lane >> 3) & 1) * 16);

    float C[2][2][4];
#pragma unroll
    for (int i = 0; i < 2; i++)
#pragma unroll
        for (int j = 0; j < 2; j++)
#pragma unroll
            for (int k = 0; k < 4; k++) C[i][j][k] = 0.f;

    float acs[8], acq[8];
#pragma unroll
    for (int u = 0; u < 8; u++) { acs[u] = 0.f; acq[u] = 0.f; }

#define LDU(u, t) __ldg((const float4*)(((u) < 4 ? P : Q) + goff[u] + (t) * KT))
#define STU(u, boff) do {                                                     \
        float4 vv = v[u];                                                     \
        u32 w0 = bpack(vv.x, vv.y), w1 = bpack(vv.z, vv.w);                   \
        asm volatile("st.shared.v2.b32 [%0], {%1,%2};"                        \
                     :: "r"(sdst[u] + (boff)), "r"(w0), "r"(w1));             \
        acs[u] += (vv.x + vv.y) + (vv.z + vv.w);                              \
        acq[u] = fmaf(vv.x, vv.x, acq[u]); acq[u] = fmaf(vv.y, vv.y, acq[u]); \
        acq[u] = fmaf(vv.z, vv.z, acq[u]); acq[u] = fmaf(vv.w, vv.w, acq[u]); \
    } while (0)

    float4 v[8];
#pragma unroll
    for (int u = 0; u < 8; u++) v[u] = LDU(u, 0);         // tile 0
#pragma unroll
    for (int u = 0; u < 8; u++) { STU(u, 0); v[u] = LDU(u, 1); }  // fill buf0, fetch tile1
    __syncthreads();                                       // buf0 ready

    for (int t = 0; t < NT; t++) {
        const u32 boff = (u32)((t & 1) * 8192);
        if (t + 1 < NT) {                                  // store t+1, fetch t+2
            const u32 woff = (u32)(((t + 1) & 1) * 8192);
#pragma unroll
            for (int u = 0; u < 8; u++) {
                STU(u, woff);
                if (t + 2 < NT) v[u] = LDU(u, t + 2);
            }
        }
#pragma unroll
        for (int j = 0; j < 4; j++) {                      // 4 x k16 on buf[t&1]
            u32 a[2][4], bq[2][2];
#pragma unroll
            for (int mt = 0; mt < 2; mt++)
                ldsm4(a[mt][0], a[mt][1], a[mt][2], a[mt][3],
                      aB[mt] + boff + (((u32)(j * 32) + c16A) ^ xm));
#pragma unroll
            for (int nt = 0; nt < 2; nt++)
                ldsm2(bq[nt][0], bq[nt][1],
                      bB[nt] + boff + (((u32)(j * 32) + c16B) ^ xm));
#pragma unroll
            for (int mt = 0; mt < 2; mt++)
#pragma unroll
                for (int nt = 0; nt < 2; nt++)
                    mma16816(C[mt][nt], a[mt][0], a[mt][1], a[mt][2], a[mt][3],
                             bq[nt][0], bq[nt][1]);
        }
        __syncthreads();                                   // one barrier per tile
    }

    // ---- write C partials (warps 0-1: PP, 2-3: PN) ----
    {
        float* g0 = (wid < 2 ? g_pp : g_pn) + ((size_t)(chunk * BB + b)) * (NW * NW);
        const int g = lane >> 2, tq = lane & 3;
        const int wcol = (wid & 1) * 16;
#pragma unroll
        for (int mt = 0; mt < 2; mt++)
#pragma unroll
            for (int nt = 0; nt < 2; nt++) {
                int row0 = 16 * mt + g;
                int cc = wcol + nt * 8 + 2 * tq;
                *(float2*)(g0 + row0 * NW + cc) = make_float2(C[mt][nt][0], C[mt][nt][1]);
                *(float2*)(g0 + (row0 + 8) * NW + cc) = make_float2(C[mt][nt][2], C[mt][nt][3]);
            }
    }

    // ---- stats: reduce within 16-lane row groups, write ----
#pragma unroll
    for (int u = 0; u < 8; u++) {
#pragma unroll
        for (int off = 1; off < 16; off <<= 1) {
            acs[u] += __shfl_xor_sync(0xffffffffu, acs[u], off);
            acq[u] += __shfl_xor_sync(0xffffffffu, acq[u], off);
        }
        if (li == 0) {
            int set = u >> 2, n = 8 * (u & 3) + lrow;
            int idx = (chunk * 2 + set) * (BB * NW) + b * NW + n;
            g_sum[idx] = acs[u];  g_sq[idx] = acq[u];
        }
    }
}

// ============================================================================
// Kernel 2: fold stats + sxy partials -> d -> expf -> reduce into g_tot.
// ============================================================================
__global__ void __launch_bounds__(256) k_dmat() {
    const int set = blockIdx.y, blk = blockIdx.x, tid = threadIdx.x;
    __shared__ float s_sx[2][BB * NW], s_rv[2][BB * NW];
#pragma unroll
    for (int side = 0; side < 2; side++) {
        int srcSet = side ? set : 0;
        for (int idx = tid; idx < BB * NW; idx += 256) {
            float s = 0.f, s2 = 0.f;
#pragma unroll
            for (int c = 0; c < KCH; c++) {
                int a = (c * 2 + srcSet) * (BB * NW) + idx;
                s += g_sum[a]; s2 += g_sq[a];
            }
            s_sx[side][idx] = s;
            s_rv[side][idx] = rsqrtf((float)TT * s2 - s * s);
        }
    }
    __syncthreads();
    const int half = tid >> 7, nml = tid & 127, nm = blk * 128 + nml;
    const int n = nm >> 5, m = nm & 31;
    const float* src = set ? g_pn : g_pp;
    float acc = 0.f;
    const int b0 = half * 32;
#pragma unroll 4
    for (int b = b0; b < b0 + 32; b++) {
        float sxy = 0.f;
#pragma unroll
        for (int c = 0; c < KCH; c++)
            sxy += src[((size_t)(c * BB + b)) * (NW * NW) + nm];
        float r = ((float)TT * sxy - s_sx[0][b * NW + n] * s_sx[1][b * NW + m])
                  * s_rv[0][b * NW + n] * s_rv[1][b * NW + m];
        acc += 1.f - r;
    }
    __shared__ float s_red[256];
    s_red[tid] = acc;
    __syncthreads();
    __shared__ double s_d[256];
    double e = 0.0;
    if (half == 0) {
        float d = (acc + s_red[128 + nml]) * (1.f / (float)BB);
        bool keep = set ? true : (m > n);
        if (keep) e = (double)expf(12.5f * d);
    }
    s_d[tid] = e;
    __syncthreads();
#pragma unroll
    for (int s = 128; s > 0; s >>= 1) {
        if (tid < s) s_d[tid] += s_d[tid + s];
        __syncthreads();
    }
    if (tid == 0) atomicAdd(&g_tot[set], s_d[0]);
}

__global__ void k_final(float* __restrict__ out) {
    out[0] = (float)log10(g_tot[0] / g_tot[1] + 1.0);
}

extern "C" void kernel_launch(void* const* d_in, const int* in_sizes, int n_in,
                              void* d_out, int out_size) {
    const float* P = (const float*)d_in[0];
    const float* Q = (const float*)d_in[1];
    k_gemm<<<dim3(KCH, BB), 128>>>(P, Q);
    k_dmat<<<dim3(8, 2), 256>>>();
    k_final<<<1, 1>>>((float*)d_out);
}